// round 1
// baseline (speedup 1.0000x reference)
#include <cuda_runtime.h>
#include <cuda_bf16.h>
#include <cstdint>

// Problem shapes (fixed by the dataset)
constexpr int M_TOK = 16384;   // b*s = 4*4096
constexpr int KDIM  = 2048;    // h
constexpr int Z     = 64;      // per-projection output dim
constexpr int NTOT  = 192;     // q|k|v concatenated

// GEMM tiling
constexpr int BM = 128;
constexpr int BN = 192;
constexpr int BK = 32;
constexpr int PAD_K = 40;      // padded K extent in smem (bank-conflict-free: 20*g+tig covers all 32 banks)
constexpr int NCHUNK = KDIM / BK;  // 64

constexpr int SM_X = BM * PAD_K;   // 5120 bf16
constexpr int SM_W = BN * PAD_K;   // 7680 bf16
constexpr int OFF_XHI = 0;
constexpr int OFF_XLO = SM_X;
constexpr int OFF_WHI = 2 * SM_X;            // 2 buffers
constexpr int OFF_WLO = 2 * SM_X + 2 * SM_W;
constexpr int SMEM_ELEMS = 2 * SM_X + 4 * SM_W;      // 40960 bf16
constexpr int SMEM_BYTES = SMEM_ELEMS * 2;           // 81920 B

// Scratch (static device allocations — allowed)
__device__ __nv_bfloat16 g_Wt_hi[(size_t)NTOT * KDIM];   // [n][k], n-major, k contiguous
__device__ __nv_bfloat16 g_Wt_lo[(size_t)NTOT * KDIM];
__device__ float g_qkv[(size_t)M_TOK * NTOT];            // [token][q0..63 | k0..63 | v0..63]

// ---------------------------------------------------------------------------
// Prep: split W into bf16 hi/lo and transpose to [n][k]
// ---------------------------------------------------------------------------
__global__ void prep_w(const float* __restrict__ Wq,
                       const float* __restrict__ Wk,
                       const float* __restrict__ Wv) {
    int idx = blockIdx.x * blockDim.x + threadIdx.x;
    if (idx >= NTOT * KDIM) return;
    int k = idx % KDIM;
    int n = idx / KDIM;
    int m = n / Z;
    int z = n % Z;
    const float* W = (m == 0) ? Wq : ((m == 1) ? Wk : Wv);
    float w = W[(size_t)k * Z + z];
    __nv_bfloat16 hi = __float2bfloat16(w);
    float lo = w - __bfloat162float(hi);
    g_Wt_hi[idx] = hi;
    g_Wt_lo[idx] = __float2bfloat16(lo);
}

// ---------------------------------------------------------------------------
// mma.sync m16n8k16 bf16 (row.col), fp32 accumulate
// ---------------------------------------------------------------------------
__device__ __forceinline__ void mma16816(float (&c)[4], const uint32_t (&a)[4],
                                         const uint32_t (&b)[2]) {
    asm volatile(
        "mma.sync.aligned.m16n8k16.row.col.f32.bf16.bf16.f32 "
        "{%0,%1,%2,%3}, {%4,%5,%6,%7}, {%8,%9}, {%0,%1,%2,%3};\n"
        : "+f"(c[0]), "+f"(c[1]), "+f"(c[2]), "+f"(c[3])
        : "r"(a[0]), "r"(a[1]), "r"(a[2]), "r"(a[3]), "r"(b[0]), "r"(b[1]));
}

__device__ __forceinline__ void cp_async16(void* dst, const void* src) {
    unsigned s = (unsigned)__cvta_generic_to_shared(dst);
    asm volatile("cp.async.cg.shared.global [%0], [%1], 16;\n" :: "r"(s), "l"(src) : "memory");
}
__device__ __forceinline__ void cp_commit() {
    asm volatile("cp.async.commit_group;\n" ::: "memory");
}

__device__ __forceinline__ uint32_t pack_bf2(__nv_bfloat16 a, __nv_bfloat16 b) {
    __nv_bfloat162 t = __halves2bfloat162(a, b);   // x=a (low), y=b (high)
    return *reinterpret_cast<uint32_t*>(&t);
}

// ---------------------------------------------------------------------------
// QKV GEMM: C[16384,192] = X[16384,2048] * Wt^T, split-bf16 (hi/lo), HMMA
// grid = 128 CTAs (one M-tile each), 256 threads (8 warps: 2 x 4 warp grid)
// ---------------------------------------------------------------------------
__global__ void __launch_bounds__(256, 1)
qkv_gemm(const float* __restrict__ X) {
    extern __shared__ __nv_bfloat16 smem[];
    __nv_bfloat16* sXhi = smem + OFF_XHI;
    __nv_bfloat16* sXlo = smem + OFF_XLO;
    __nv_bfloat16* sWhi = smem + OFF_WHI;
    __nv_bfloat16* sWlo = smem + OFF_WLO;

    const int tid  = threadIdx.x;
    const int lane = tid & 31;
    const int wid  = tid >> 5;
    const int g    = lane >> 2;
    const int tig  = lane & 3;
    const int warp_m = (wid & 1) * 64;     // 2 warp rows of 64
    const int warp_n = (wid >> 1) * 48;    // 4 warp cols of 48
    const int m0 = blockIdx.x * BM;

    // X prefetch assignment: 2 threads per row, 16 consecutive floats each
    const int xr = tid >> 1;
    const int xk = (tid & 1) * 16;

    float acc[4][6][4];
#pragma unroll
    for (int mt = 0; mt < 4; mt++)
#pragma unroll
        for (int nt = 0; nt < 6; nt++)
#pragma unroll
            for (int r = 0; r < 4; r++) acc[mt][nt][r] = 0.f;

    float4 xf[4];

    // --- prologue: W chunk 0 via cp.async, X chunk 0 into registers ---
    {
#pragma unroll
        for (int r = 0; r < 3; r++) {
            int u = tid + r * 256;           // 0..767: n = u/4, 16B quad = u%4
            int n = u >> 2, q = u & 3;
            cp_async16(sWhi + n * PAD_K + q * 8,
                       g_Wt_hi + (size_t)n * KDIM + q * 8);
            cp_async16(sWlo + n * PAD_K + q * 8,
                       g_Wt_lo + (size_t)n * KDIM + q * 8);
        }
        cp_commit();
        const float4* p = reinterpret_cast<const float4*>(
            X + (size_t)(m0 + xr) * KDIM + xk);
        xf[0] = p[0]; xf[1] = p[1]; xf[2] = p[2]; xf[3] = p[3];
    }

#pragma unroll 1
    for (int c = 0; c < NCHUNK; ++c) {
        const int buf = c & 1;
        __syncthreads();   // prior compute done reading sX and sW[buf^1]

        // issue W chunk c+1 into the other buffer (overlaps with compute below)
        if (c + 1 < NCHUNK) {
            const size_t koff = (size_t)(c + 1) * BK;
            __nv_bfloat16* dh = sWhi + (buf ^ 1) * SM_W;
            __nv_bfloat16* dl = sWlo + (buf ^ 1) * SM_W;
#pragma unroll
            for (int r = 0; r < 3; r++) {
                int u = tid + r * 256;
                int n = u >> 2, q = u & 3;
                cp_async16(dh + n * PAD_K + q * 8,
                           g_Wt_hi + (size_t)n * KDIM + koff + q * 8);
                cp_async16(dl + n * PAD_K + q * 8,
                           g_Wt_lo + (size_t)n * KDIM + koff + q * 8);
            }
            cp_commit();
        }

        // store X chunk c (hi/lo split) to smem
        {
            float v[16];
            v[0]=xf[0].x; v[1]=xf[0].y; v[2]=xf[0].z; v[3]=xf[0].w;
            v[4]=xf[1].x; v[5]=xf[1].y; v[6]=xf[1].z; v[7]=xf[1].w;
            v[8]=xf[2].x; v[9]=xf[2].y; v[10]=xf[2].z; v[11]=xf[2].w;
            v[12]=xf[3].x; v[13]=xf[3].y; v[14]=xf[3].z; v[15]=xf[3].w;
            uint32_t hw[8], lw[8];
#pragma unroll
            for (int p = 0; p < 8; p++) {
                float a = v[2 * p], b = v[2 * p + 1];
                __nv_bfloat16 ha = __float2bfloat16(a);
                __nv_bfloat16 hb = __float2bfloat16(b);
                float la = a - __bfloat162float(ha);
                float lb = b - __bfloat162float(hb);
                hw[p] = pack_bf2(ha, hb);
                lw[p] = pack_bf2(__float2bfloat16(la), __float2bfloat16(lb));
            }
            uint4* dsth = reinterpret_cast<uint4*>(sXhi + xr * PAD_K + xk);
            uint4* dstl = reinterpret_cast<uint4*>(sXlo + xr * PAD_K + xk);
            dsth[0] = make_uint4(hw[0], hw[1], hw[2], hw[3]);
            dsth[1] = make_uint4(hw[4], hw[5], hw[6], hw[7]);
            dstl[0] = make_uint4(lw[0], lw[1], lw[2], lw[3]);
            dstl[1] = make_uint4(lw[4], lw[5], lw[6], lw[7]);
        }

        // prefetch X chunk c+1 into registers
        if (c + 1 < NCHUNK) {
            const float4* p = reinterpret_cast<const float4*>(
                X + (size_t)(m0 + xr) * KDIM + (size_t)(c + 1) * BK + xk);
            xf[0] = p[0]; xf[1] = p[1]; xf[2] = p[2]; xf[3] = p[3];
        }

        // wait for W chunk c, then make everything visible
        if (c + 1 < NCHUNK) { asm volatile("cp.async.wait_group 1;\n" ::: "memory"); }
        else                { asm volatile("cp.async.wait_group 0;\n" ::: "memory"); }
        __syncthreads();

        // --- compute on chunk c ---
        const __nv_bfloat16* Wh = sWhi + buf * SM_W;
        const __nv_bfloat16* Wl = sWlo + buf * SM_W;
#pragma unroll
        for (int kk = 0; kk < BK; kk += 16) {
            uint32_t a[4][4], bh[6][2], bl[6][2];
#pragma unroll
            for (int nt = 0; nt < 6; nt++) {
                int n = warp_n + nt * 8 + g;
                const __nv_bfloat16* ph = Wh + n * PAD_K + kk + 2 * tig;
                const __nv_bfloat16* pl = Wl + n * PAD_K + kk + 2 * tig;
                bh[nt][0] = *reinterpret_cast<const uint32_t*>(ph);
                bh[nt][1] = *reinterpret_cast<const uint32_t*>(ph + 8);
                bl[nt][0] = *reinterpret_cast<const uint32_t*>(pl);
                bl[nt][1] = *reinterpret_cast<const uint32_t*>(pl + 8);
            }
#pragma unroll
            for (int mt = 0; mt < 4; mt++) {
                int mr = warp_m + mt * 16 + g;
                const __nv_bfloat16* pa = sXhi + mr * PAD_K + kk + 2 * tig;
                a[mt][0] = *reinterpret_cast<const uint32_t*>(pa);
                a[mt][1] = *reinterpret_cast<const uint32_t*>(pa + 8 * PAD_K);
                a[mt][2] = *reinterpret_cast<const uint32_t*>(pa + 8);
                a[mt][3] = *reinterpret_cast<const uint32_t*>(pa + 8 * PAD_K + 8);
            }
            // hi*hi + hi*lo
#pragma unroll
            for (int mt = 0; mt < 4; mt++)
#pragma unroll
                for (int nt = 0; nt < 6; nt++) {
                    mma16816(acc[mt][nt], a[mt], bh[nt]);
                    mma16816(acc[mt][nt], a[mt], bl[nt]);
                }
            // lo*hi (reuse a regs for X_lo)
#pragma unroll
            for (int mt = 0; mt < 4; mt++) {
                int mr = warp_m + mt * 16 + g;
                const __nv_bfloat16* pa = sXlo + mr * PAD_K + kk + 2 * tig;
                a[mt][0] = *reinterpret_cast<const uint32_t*>(pa);
                a[mt][1] = *reinterpret_cast<const uint32_t*>(pa + 8 * PAD_K);
                a[mt][2] = *reinterpret_cast<const uint32_t*>(pa + 8);
                a[mt][3] = *reinterpret_cast<const uint32_t*>(pa + 8 * PAD_K + 8);
            }
#pragma unroll
            for (int mt = 0; mt < 4; mt++)
#pragma unroll
                for (int nt = 0; nt < 6; nt++)
                    mma16816(acc[mt][nt], a[mt], bh[nt]);
        }
    }

    // epilogue: write q|k|v to scratch
#pragma unroll
    for (int mt = 0; mt < 4; mt++) {
#pragma unroll
        for (int nt = 0; nt < 6; nt++) {
            int r  = m0 + warp_m + mt * 16 + g;
            int cn = warp_n + nt * 8 + 2 * tig;
            float2 v0 = make_float2(acc[mt][nt][0], acc[mt][nt][1]);
            float2 v1 = make_float2(acc[mt][nt][2], acc[mt][nt][3]);
            *reinterpret_cast<float2*>(&g_qkv[(size_t)r * NTOT + cn]) = v0;
            *reinterpret_cast<float2*>(&g_qkv[(size_t)(r + 8) * NTOT + cn]) = v1;
        }
    }
}

// ---------------------------------------------------------------------------
// Per-token attention: out[i] = sum_j softmax_j(q_i*k_j) * v_j
// block = 256 threads = 4 tokens x 64 lanes
// ---------------------------------------------------------------------------
__device__ __forceinline__ float ex2f(float x) {
    float y;
    asm("ex2.approx.ftz.f32 %0, %1;" : "=f"(y) : "f"(x));
    return y;
}

__global__ void __launch_bounds__(256)
attn_kernel(float* __restrict__ out) {
    __shared__ float ks[4][64];
    __shared__ float vs[4][64];
    const int tid = threadIdx.x;
    const int tl = tid >> 6;
    const int i  = tid & 63;
    const size_t tok = (size_t)blockIdx.x * 4 + tl;
    const float* base = g_qkv + tok * NTOT;

    float q = base[i] * 1.4426950408889634f;   // fold log2(e) so ex2 == exp
    ks[tl][i] = base[64 + i];
    vs[tl][i] = base[128 + i];
    __syncthreads();

    float mx = -1e30f;
#pragma unroll
    for (int j = 0; j < 64; j++) mx = fmaxf(mx, q * ks[tl][j]);

    float s = 0.f, num = 0.f;
#pragma unroll
    for (int j = 0; j < 64; j++) {
        float e = ex2f(fmaf(q, ks[tl][j], -mx));
        s += e;
        num = fmaf(e, vs[tl][j], num);
    }
    out[tok * 64 + i] = num / s;
}

// ---------------------------------------------------------------------------
extern "C" void kernel_launch(void* const* d_in, const int* in_sizes, int n_in,
                              void* d_out, int out_size) {
    const float* X  = (const float*)d_in[0];
    const float* Wq = (const float*)d_in[1];
    const float* Wk = (const float*)d_in[2];
    const float* Wv = (const float*)d_in[3];
    float* out = (float*)d_out;

    cudaFuncSetAttribute(qkv_gemm, cudaFuncAttributeMaxDynamicSharedMemorySize,
                         SMEM_BYTES);

    prep_w<<<(NTOT * KDIM + 255) / 256, 256>>>(Wq, Wk, Wv);
    qkv_gemm<<<M_TOK / BM, 256, SMEM_BYTES>>>(X);
    attn_kernel<<<M_TOK / 4, 256>>>(out);
}

// round 3
// speedup vs baseline: 1.0727x; 1.0727x over previous
#include <cuda_runtime.h>
#include <cuda_bf16.h>
#include <cstdint>

// Problem shapes (fixed by the dataset)
constexpr int M_TOK = 16384;   // b*s = 4*4096
constexpr int KDIM  = 2048;    // h
constexpr int Z     = 64;      // per-projection output dim
constexpr int NTOT  = 192;     // q|k|v concatenated

// GEMM tiling
constexpr int BM = 128;
constexpr int BN = 192;
constexpr int BK = 32;
constexpr int PAD_K = 40;      // padded K extent (row = 80 B: 16B-aligned, LDSM conflict-free)
constexpr int NCHUNK = KDIM / BK;  // 64

constexpr int SM_X = BM * PAD_K;   // 5120 bf16
constexpr int SM_W = BN * PAD_K;   // 7680 bf16
constexpr int OFF_XHI = 0;
constexpr int OFF_XLO = SM_X;
constexpr int OFF_WHI = 2 * SM_X;            // 2 buffers
constexpr int OFF_WLO = 2 * SM_X + 2 * SM_W;
constexpr int SMEM_ELEMS = 2 * SM_X + 4 * SM_W;      // 40960 bf16
constexpr int SMEM_BYTES = SMEM_ELEMS * 2;           // 81920 B

// Scratch (static device arrays — allowed)
__device__ __nv_bfloat16 g_Wt_hi[(size_t)NTOT * KDIM];   // [n][k]
__device__ __nv_bfloat16 g_Wt_lo[(size_t)NTOT * KDIM];
__device__ float g_qkv[(size_t)M_TOK * NTOT];            // [token][q|k|v]

// ---------------------------------------------------------------- helpers
__device__ __forceinline__ void mma16816(float (&c)[4], const uint32_t (&a)[4],
                                         uint32_t b0, uint32_t b1) {
    asm volatile(
        "mma.sync.aligned.m16n8k16.row.col.f32.bf16.bf16.f32 "
        "{%0,%1,%2,%3}, {%4,%5,%6,%7}, {%8,%9}, {%0,%1,%2,%3};\n"
        : "+f"(c[0]), "+f"(c[1]), "+f"(c[2]), "+f"(c[3])
        : "r"(a[0]), "r"(a[1]), "r"(a[2]), "r"(a[3]), "r"(b0), "r"(b1));
}

__device__ __forceinline__ void ldsm4(uint32_t (&r)[4], uint32_t addr) {
    asm volatile("ldmatrix.sync.aligned.m8n8.x4.shared.b16 {%0,%1,%2,%3}, [%4];"
                 : "=r"(r[0]), "=r"(r[1]), "=r"(r[2]), "=r"(r[3]) : "r"(addr));
}

__device__ __forceinline__ void cp_async16(uint32_t dst, const void* src) {
    asm volatile("cp.async.cg.shared.global [%0], [%1], 16;\n" :: "r"(dst), "l"(src) : "memory");
}
__device__ __forceinline__ void cp_commit() {
    asm volatile("cp.async.commit_group;\n" ::: "memory");
}
__device__ __forceinline__ uint32_t pack_bf2(__nv_bfloat16 a, __nv_bfloat16 b) {
    __nv_bfloat162 t = __halves2bfloat162(a, b);
    return *reinterpret_cast<uint32_t*>(&t);
}

// ---------------------------------------------------------------- prep_w
// Tiled transpose W(h,z) -> Wt[n][k] + bf16 hi/lo split. Coalesced both ways.
__global__ void prep_w(const float* __restrict__ Wq,
                       const float* __restrict__ Wk,
                       const float* __restrict__ Wv) {
    __shared__ float s[64][65];
    const int m  = blockIdx.x / 32;          // which matrix
    const int k0 = (blockIdx.x % 32) * 64;   // k tile
    const float* W = (m == 0) ? Wq : ((m == 1) ? Wk : Wv);
    const int t = threadIdx.x;
#pragma unroll
    for (int i = 0; i < 16; i++) {
        int u = t + i * 256;
        int kl = u >> 6, z = u & 63;
        s[kl][z] = W[(size_t)(k0 + kl) * 64 + z];   // coalesced read
    }
    __syncthreads();
#pragma unroll
    for (int i = 0; i < 16; i++) {
        int u = t + i * 256;
        int z = u >> 6, kl = u & 63;
        float w = s[kl][z];
        __nv_bfloat16 hi = __float2bfloat16(w);
        float lo = w - __bfloat162float(hi);
        size_t o = (size_t)(m * 64 + z) * KDIM + k0 + kl;  // coalesced write
        g_Wt_hi[o] = hi;
        g_Wt_lo[o] = __float2bfloat16(lo);
    }
}

// ---------------------------------------------------------------- QKV GEMM
// C[16384,192] = X * Wt^T, split-bf16 (hi*hi + hi*lo + lo*hi), HMMA + LDSM.
// grid = 128 CTAs (one 128-row M tile), 256 threads (2x4 warp grid).
__global__ void __launch_bounds__(256, 1)
qkv_gemm(const float* __restrict__ X) {
    extern __shared__ __nv_bfloat16 smem[];
    __nv_bfloat16* sXhi = smem + OFF_XHI;
    __nv_bfloat16* sXlo = smem + OFF_XLO;
    __nv_bfloat16* sWhi = smem + OFF_WHI;
    __nv_bfloat16* sWlo = smem + OFF_WLO;

    const int tid  = threadIdx.x;
    const int lane = tid & 31;
    const int wid  = tid >> 5;
    const int g    = lane >> 2;
    const int tig  = lane & 3;
    const int warp_m = (wid & 1) * 64;     // 2 warp rows of 64
    const int warp_n = (wid >> 1) * 48;    // 4 warp cols of 48
    const int m0 = blockIdx.x * BM;

    // ldmatrix lane-address components
    const int lrow = lane & 7;
    const int lbit3 = (lane >> 3) & 1;
    const int lbit4 = (lane >> 4) & 1;

    // A (x4 = 16x16 tile): matrices [rows0-7,k0-7][rows8-15,k0-7][rows0-7,k8-15][rows8-15,k8-15]
    uint32_t aHiA[4], aLoA[4];
#pragma unroll
    for (int mt = 0; mt < 4; mt++) {
        int row = warp_m + mt * 16 + lrow + lbit3 * 8;
        uint32_t off = (uint32_t)row * 80u + (uint32_t)lbit4 * 16u;
        aHiA[mt] = (uint32_t)__cvta_generic_to_shared(sXhi) + off;
        aLoA[mt] = (uint32_t)__cvta_generic_to_shared(sXlo) + off;
    }
    // B (x4 = 16 n-rows x 16 k): matrices [n0-7,k0-7][n0-7,k8-15][n8-15,k0-7][n8-15,k8-15]
    uint32_t bHiA[3], bLoA[3];
#pragma unroll
    for (int p = 0; p < 3; p++) {
        int row = warp_n + p * 16 + lrow + lbit4 * 8;
        uint32_t off = (uint32_t)row * 80u + (uint32_t)lbit3 * 16u;
        bHiA[p] = (uint32_t)__cvta_generic_to_shared(sWhi) + off;
        bLoA[p] = (uint32_t)__cvta_generic_to_shared(sWlo) + off;
    }

    // W cp.async destinations (bank-friendly, swizzle-free padded layout)
    const uint32_t sWhiB = (uint32_t)__cvta_generic_to_shared(sWhi);
    const uint32_t sWloB = (uint32_t)__cvta_generic_to_shared(sWlo);

    // X prefetch assignment: 2 threads per row, 16 consecutive floats each
    const int xr = tid >> 1;
    const int xk = (tid & 1) * 16;

    float acc[4][6][4];
#pragma unroll
    for (int mt = 0; mt < 4; mt++)
#pragma unroll
        for (int nt = 0; nt < 6; nt++)
#pragma unroll
            for (int r = 0; r < 4; r++) acc[mt][nt][r] = 0.f;

    float4 xf[4];

    // --- prologue: W chunk 0 via cp.async, X chunk 0 into registers ---
    {
#pragma unroll
        for (int r = 0; r < 3; r++) {
            int u = tid + r * 256;           // 0..767: n = u/4, 16B quad = u%4
            int n = u >> 2, q = u & 3;
            uint32_t d = (uint32_t)n * 80u + (uint32_t)q * 16u;
            cp_async16(sWhiB + d, g_Wt_hi + (size_t)n * KDIM + q * 8);
            cp_async16(sWloB + d, g_Wt_lo + (size_t)n * KDIM + q * 8);
        }
        cp_commit();
        const float4* p = reinterpret_cast<const float4*>(
            X + (size_t)(m0 + xr) * KDIM + xk);
        xf[0] = p[0]; xf[1] = p[1]; xf[2] = p[2]; xf[3] = p[3];
    }

#pragma unroll 1
    for (int c = 0; c < NCHUNK; ++c) {
        const int buf = c & 1;
        const uint32_t wOff = (uint32_t)buf * (SM_W * 2);   // byte offset of W buffer
        __syncthreads();   // previous compute done reading sX and sW[buf^1]

        // issue W chunk c+1 into the other buffer
        if (c + 1 < NCHUNK) {
            const size_t koff = (size_t)(c + 1) * BK;
            const uint32_t dOff = (uint32_t)(buf ^ 1) * (SM_W * 2);
#pragma unroll
            for (int r = 0; r < 3; r++) {
                int u = tid + r * 256;
                int n = u >> 2, q = u & 3;
                uint32_t d = (uint32_t)n * 80u + (uint32_t)q * 16u + dOff;
                cp_async16(sWhiB + d, g_Wt_hi + (size_t)n * KDIM + koff + q * 8);
                cp_async16(sWloB + d, g_Wt_lo + (size_t)n * KDIM + koff + q * 8);
            }
            cp_commit();
        }

        // store X chunk c (hi/lo split) to smem
        {
            float v[16];
            v[0]=xf[0].x; v[1]=xf[0].y; v[2]=xf[0].z; v[3]=xf[0].w;
            v[4]=xf[1].x; v[5]=xf[1].y; v[6]=xf[1].z; v[7]=xf[1].w;
            v[8]=xf[2].x; v[9]=xf[2].y; v[10]=xf[2].z; v[11]=xf[2].w;
            v[12]=xf[3].x; v[13]=xf[3].y; v[14]=xf[3].z; v[15]=xf[3].w;
            uint32_t hw[8], lw[8];
#pragma unroll
            for (int p = 0; p < 8; p++) {
                float a = v[2 * p], b = v[2 * p + 1];
                __nv_bfloat16 ha = __float2bfloat16(a);
                __nv_bfloat16 hb = __float2bfloat16(b);
                float la = a - __bfloat162float(ha);
                float lb = b - __bfloat162float(hb);
                hw[p] = pack_bf2(ha, hb);
                lw[p] = pack_bf2(__float2bfloat16(la), __float2bfloat16(lb));
            }
            uint4* dsth = reinterpret_cast<uint4*>(sXhi + xr * PAD_K + xk);
            uint4* dstl = reinterpret_cast<uint4*>(sXlo + xr * PAD_K + xk);
            dsth[0] = make_uint4(hw[0], hw[1], hw[2], hw[3]);
            dsth[1] = make_uint4(hw[4], hw[5], hw[6], hw[7]);
            dstl[0] = make_uint4(lw[0], lw[1], lw[2], lw[3]);
            dstl[1] = make_uint4(lw[4], lw[5], lw[6], lw[7]);
        }

        // prefetch X chunk c+1 into registers
        if (c + 1 < NCHUNK) {
            const float4* p = reinterpret_cast<const float4*>(
                X + (size_t)(m0 + xr) * KDIM + (size_t)(c + 1) * BK + xk);
            xf[0] = p[0]; xf[1] = p[1]; xf[2] = p[2]; xf[3] = p[3];
        }

        if (c + 1 < NCHUNK) { asm volatile("cp.async.wait_group 1;\n" ::: "memory"); }
        else                { asm volatile("cp.async.wait_group 0;\n" ::: "memory"); }
        __syncthreads();

        // --- compute on chunk c: three separated passes, no back-to-back acc reuse
#pragma unroll
        for (int kk2 = 0; kk2 < 2; kk2++) {
            const uint32_t kb = kk2 * 32;   // bytes (16 bf16)

            uint32_t ah[4][4], bh[3][4], bl[3][4];
#pragma unroll
            for (int mt = 0; mt < 4; mt++) ldsm4(ah[mt], aHiA[mt] + kb);
#pragma unroll
            for (int p = 0; p < 3; p++)    ldsm4(bh[p], bHiA[p] + wOff + kb);
#pragma unroll
            for (int p = 0; p < 3; p++)    ldsm4(bl[p], bLoA[p] + wOff + kb);

            // pass 1: hi*hi
#pragma unroll
            for (int mt = 0; mt < 4; mt++)
#pragma unroll
                for (int nt = 0; nt < 6; nt++)
                    mma16816(acc[mt][nt], ah[mt],
                             bh[nt >> 1][(nt & 1) * 2], bh[nt >> 1][(nt & 1) * 2 + 1]);
            // pass 2: hi*lo
#pragma unroll
            for (int mt = 0; mt < 4; mt++)
#pragma unroll
                for (int nt = 0; nt < 6; nt++)
                    mma16816(acc[mt][nt], ah[mt],
                             bl[nt >> 1][(nt & 1) * 2], bl[nt >> 1][(nt & 1) * 2 + 1]);
            // pass 3: lo*hi
            uint32_t al[4][4];
#pragma unroll
            for (int mt = 0; mt < 4; mt++) ldsm4(al[mt], aLoA[mt] + kb);
#pragma unroll
            for (int mt = 0; mt < 4; mt++)
#pragma unroll
                for (int nt = 0; nt < 6; nt++)
                    mma16816(acc[mt][nt], al[mt],
                             bh[nt >> 1][(nt & 1) * 2], bh[nt >> 1][(nt & 1) * 2 + 1]);
        }
    }

    // epilogue: write q|k|v to scratch
#pragma unroll
    for (int mt = 0; mt < 4; mt++) {
#pragma unroll
        for (int nt = 0; nt < 6; nt++) {
            int r  = m0 + warp_m + mt * 16 + g;
            int cn = warp_n + nt * 8 + 2 * tig;
            float2 v0 = make_float2(acc[mt][nt][0], acc[mt][nt][1]);
            float2 v1 = make_float2(acc[mt][nt][2], acc[mt][nt][3]);
            *reinterpret_cast<float2*>(&g_qkv[(size_t)r * NTOT + cn]) = v0;
            *reinterpret_cast<float2*>(&g_qkv[(size_t)(r + 8) * NTOT + cn]) = v1;
        }
    }
}

// ---------------------------------------------------------------- attention
__device__ __forceinline__ float ex2f(float x) {
    float y;
    asm("ex2.approx.ftz.f32 %0, %1;" : "=f"(y) : "f"(x));
    return y;
}

__global__ void __launch_bounds__(256)
attn_kernel(float* __restrict__ out) {
    __shared__ float ks[4][64];
    __shared__ float vs[4][64];
    const int tid = threadIdx.x;
    const int tl = tid >> 6;
    const int i  = tid & 63;
    const size_t tok = (size_t)blockIdx.x * 4 + tl;
    const float* base = g_qkv + tok * NTOT;

    float q = base[i] * 1.4426950408889634f;   // fold log2(e)
    ks[tl][i] = base[64 + i];
    vs[tl][i] = base[128 + i];
    __syncthreads();

    float mx = -1e30f;
#pragma unroll
    for (int j = 0; j < 64; j++) mx = fmaxf(mx, q * ks[tl][j]);

    float s = 0.f, num = 0.f;
#pragma unroll
    for (int j = 0; j < 64; j++) {
        float e = ex2f(fmaf(q, ks[tl][j], -mx));
        s += e;
        num = fmaf(e, vs[tl][j], num);
    }
    out[tok * 64 + i] = num / s;
}

// ----------------------------------------------------------------
extern "C" void kernel_launch(void* const* d_in, const int* in_sizes, int n_in,
                              void* d_out, int out_size) {
    const float* X  = (const float*)d_in[0];
    const float* Wq = (const float*)d_in[1];
    const float* Wk = (const float*)d_in[2];
    const float* Wv = (const float*)d_in[3];
    float* out = (float*)d_out;

    cudaFuncSetAttribute(qkv_gemm, cudaFuncAttributeMaxDynamicSharedMemorySize,
                         SMEM_BYTES);

    prep_w<<<96, 256>>>(Wq, Wk, Wv);
    qkv_gemm<<<M_TOK / BM, 256, SMEM_BYTES>>>(X);
    attn_kernel<<<M_TOK / 4, 256>>>(out);
}

// round 4
// speedup vs baseline: 1.0879x; 1.0142x over previous
#include <cuda_runtime.h>
#include <cuda_bf16.h>
#include <cstdint>

// Problem shapes (fixed by the dataset)
constexpr int M_TOK = 16384;   // b*s = 4*4096
constexpr int KDIM  = 2048;    // h
constexpr int NTOT  = 192;     // q|k|v concatenated

// GEMM tiling
constexpr int BM = 128;
constexpr int BN = 192;
constexpr int BK = 32;
constexpr int PAD_K = 40;      // row = 80 B (16B-aligned, LDSM conflict-free)
constexpr int NCHUNK = KDIM / BK;  // 64

constexpr int SM_X = BM * PAD_K;   // 5120 bf16 (one X half: hi or lo)
constexpr int SM_W = BN * PAD_K;   // 7680 bf16

// Double-buffered X (hi+lo) then double-buffered W (hi+lo)
// X region: buf0{hi,lo}, buf1{hi,lo}; W region likewise.
constexpr int XBUF_STRIDE_B = 2 * SM_X * 2;       // 20480 B per X buffer (hi+lo)
constexpr int WBUF_STRIDE_B = 2 * SM_W * 2;       // 30720 B per W buffer (hi+lo)
constexpr int OFF_X_B = 0;
constexpr int OFF_W_B = 2 * XBUF_STRIDE_B;        // 40960
constexpr int SMEM_BYTES = 2 * XBUF_STRIDE_B + 2 * WBUF_STRIDE_B;  // 102400 B

// Scratch
__device__ __nv_bfloat16 g_Wt_hi[(size_t)NTOT * KDIM];   // [n][k]
__device__ __nv_bfloat16 g_Wt_lo[(size_t)NTOT * KDIM];
__device__ float g_qkv[(size_t)M_TOK * NTOT];

// ---------------------------------------------------------------- helpers
__device__ __forceinline__ void mma16816(float (&c)[4], const uint32_t (&a)[4],
                                         uint32_t b0, uint32_t b1) {
    asm volatile(
        "mma.sync.aligned.m16n8k16.row.col.f32.bf16.bf16.f32 "
        "{%0,%1,%2,%3}, {%4,%5,%6,%7}, {%8,%9}, {%0,%1,%2,%3};\n"
        : "+f"(c[0]), "+f"(c[1]), "+f"(c[2]), "+f"(c[3])
        : "r"(a[0]), "r"(a[1]), "r"(a[2]), "r"(a[3]), "r"(b0), "r"(b1));
}
__device__ __forceinline__ void ldsm4(uint32_t (&r)[4], uint32_t addr) {
    asm volatile("ldmatrix.sync.aligned.m8n8.x4.shared.b16 {%0,%1,%2,%3}, [%4];"
                 : "=r"(r[0]), "=r"(r[1]), "=r"(r[2]), "=r"(r[3]) : "r"(addr));
}
__device__ __forceinline__ void cp_async16(uint32_t dst, const void* src) {
    asm volatile("cp.async.cg.shared.global [%0], [%1], 16;\n" :: "r"(dst), "l"(src) : "memory");
}
__device__ __forceinline__ void cp_commit() {
    asm volatile("cp.async.commit_group;\n" ::: "memory");
}
__device__ __forceinline__ uint32_t cvt_bf16x2(float a, float b) {  // pack (a lo, b hi)
    uint32_t r;
    asm("cvt.rn.bf16x2.f32 %0, %1, %2;" : "=r"(r) : "f"(b), "f"(a));
    return r;
}

// ---------------------------------------------------------------- prep_w
// Tiled transpose W(h,z) -> Wt[n][k] + bf16 hi/lo split. 192 blocks.
__global__ void prep_w(const float* __restrict__ Wq,
                       const float* __restrict__ Wk,
                       const float* __restrict__ Wv) {
    __shared__ float s[32][65];
    const int m  = blockIdx.x / 64;          // matrix
    const int k0 = (blockIdx.x % 64) * 32;   // k tile
    const float* W = (m == 0) ? Wq : ((m == 1) ? Wk : Wv);
    const int t = threadIdx.x;
#pragma unroll
    for (int i = 0; i < 8; i++) {
        int u = t + i * 256;
        int kl = u >> 6, z = u & 63;
        s[kl][z] = W[(size_t)(k0 + kl) * 64 + z];   // coalesced read
    }
    __syncthreads();
#pragma unroll
    for (int i = 0; i < 8; i++) {
        int u = t + i * 256;
        int z = u >> 5, kl = u & 31;
        float w = s[kl][z];
        __nv_bfloat16 hi = __float2bfloat16(w);
        float lo = w - __bfloat162float(hi);
        size_t o = (size_t)(m * 64 + z) * KDIM + k0 + kl;  // coalesced write
        g_Wt_hi[o] = hi;
        g_Wt_lo[o] = __float2bfloat16(lo);
    }
}

// ---------------------------------------------------------------- QKV GEMM
__global__ void __launch_bounds__(256, 1)
qkv_gemm(const float* __restrict__ X) {
    extern __shared__ __nv_bfloat16 smem[];
    const uint32_t sbase = (uint32_t)__cvta_generic_to_shared(smem);

    const int tid  = threadIdx.x;
    const int lane = tid & 31;
    const int wid  = tid >> 5;
    const int g    = lane >> 2;
    const int tig  = lane & 3;
    const int warp_m = (wid & 1) * 64;
    const int warp_n = (wid >> 1) * 48;
    const int m0 = blockIdx.x * BM;

    // ldmatrix lane-address components
    const int lrow = lane & 7;
    const int lbit3 = (lane >> 3) & 1;
    const int lbit4 = (lane >> 4) & 1;

    // A fragment base addrs (within buffer 0); hi at +0, lo at +SM_X*2
    uint32_t aA[4];
#pragma unroll
    for (int mt = 0; mt < 4; mt++) {
        int row = warp_m + mt * 16 + lrow + lbit3 * 8;
        aA[mt] = sbase + OFF_X_B + (uint32_t)row * 80u + (uint32_t)lbit4 * 16u;
    }
    // B fragment base addrs (within buffer 0)
    uint32_t bA[3];
#pragma unroll
    for (int p = 0; p < 3; p++) {
        int row = warp_n + p * 16 + lrow + lbit4 * 8;
        bA[p] = sbase + OFF_W_B + (uint32_t)row * 80u + (uint32_t)lbit3 * 16u;
    }

    // X load/store assignment: 2 threads per row, 16 consecutive floats
    const int xr = tid >> 1;
    const int xk = (tid & 1) * 16;
    const uint32_t xsts = sbase + OFF_X_B + (uint32_t)xr * 80u + (uint32_t)xk * 2u;
    const float* xsrc_row = X + (size_t)(m0 + xr) * KDIM + xk;

    // W cp.async assignment
    const uint32_t wdst0 = sbase + OFF_W_B;

    float acc[4][6][4];
#pragma unroll
    for (int mt = 0; mt < 4; mt++)
#pragma unroll
        for (int nt = 0; nt < 6; nt++)
#pragma unroll
            for (int r = 0; r < 4; r++) acc[mt][nt][r] = 0.f;

    float4 xf[4];

    // convert xf -> hi/lo bf16 and STS into X buffer `dOff`
    auto convert_sts = [&](uint32_t dOff) {
        float v[16] = {xf[0].x, xf[0].y, xf[0].z, xf[0].w,
                       xf[1].x, xf[1].y, xf[1].z, xf[1].w,
                       xf[2].x, xf[2].y, xf[2].z, xf[2].w,
                       xf[3].x, xf[3].y, xf[3].z, xf[3].w};
        uint32_t hw[8], lw[8];
#pragma unroll
        for (int p = 0; p < 8; p++) {
            float a = v[2 * p], b = v[2 * p + 1];
            uint32_t h = cvt_bf16x2(a, b);
            float ha = __bfloat162float(((__nv_bfloat162*)&h)->x);
            float hb = __bfloat162float(((__nv_bfloat162*)&h)->y);
            hw[p] = h;
            lw[p] = cvt_bf16x2(a - ha, b - hb);
        }
        uint32_t dh = xsts + dOff;
        uint32_t dl = dh + SM_X * 2;
        asm volatile("st.shared.v4.b32 [%0], {%1,%2,%3,%4};" ::
                     "r"(dh), "r"(hw[0]), "r"(hw[1]), "r"(hw[2]), "r"(hw[3]));
        asm volatile("st.shared.v4.b32 [%0], {%1,%2,%3,%4};" ::
                     "r"(dh + 16), "r"(hw[4]), "r"(hw[5]), "r"(hw[6]), "r"(hw[7]));
        asm volatile("st.shared.v4.b32 [%0], {%1,%2,%3,%4};" ::
                     "r"(dl), "r"(lw[0]), "r"(lw[1]), "r"(lw[2]), "r"(lw[3]));
        asm volatile("st.shared.v4.b32 [%0], {%1,%2,%3,%4};" ::
                     "r"(dl + 16), "r"(lw[4]), "r"(lw[5]), "r"(lw[6]), "r"(lw[7]));
    };

    auto ldg_x = [&](int c) {
        const float4* p = reinterpret_cast<const float4*>(xsrc_row + (size_t)c * BK);
        xf[0] = p[0]; xf[1] = p[1]; xf[2] = p[2]; xf[3] = p[3];
    };

    auto issue_w = [&](int c) {   // cp.async W(c) into wbuf[c&1]
        const size_t koff = (size_t)c * BK;
        const uint32_t dOff = (uint32_t)(c & 1) * WBUF_STRIDE_B;
#pragma unroll
        for (int r = 0; r < 3; r++) {
            int u = tid + r * 256;
            int n = u >> 2, q = u & 3;
            uint32_t d = wdst0 + dOff + (uint32_t)n * 80u + (uint32_t)q * 16u;
            cp_async16(d, g_Wt_hi + (size_t)n * KDIM + koff + q * 8);
            cp_async16(d + SM_W * 2, g_Wt_lo + (size_t)n * KDIM + koff + q * 8);
        }
        cp_commit();
    };

    // --- prologue ---
    issue_w(0);
    ldg_x(0);
    convert_sts(0);            // X(0) -> xbuf0   (stalls on LDG once)
    ldg_x(1);                  // X(1) -> regs
    asm volatile("cp.async.wait_group 0;\n" ::: "memory");
    __syncthreads();

#pragma unroll 1
    for (int c = 0; c < NCHUNK; ++c) {
        const uint32_t xOff = (uint32_t)(c & 1) * XBUF_STRIDE_B;
        const uint32_t wOff = (uint32_t)(c & 1) * WBUF_STRIDE_B;

        // (a) store X(c+1) into the idle x buffer
        if (c + 1 < NCHUNK) convert_sts((uint32_t)((c + 1) & 1) * XBUF_STRIDE_B);
        // (b) prefetch X(c+2)
        if (c + 2 < NCHUNK) ldg_x(c + 2);
        // (c) prefetch W(c+1) into the idle w buffer
        if (c + 1 < NCHUNK) issue_w(c + 1);

        // (d) compute chunk c: three separated passes
#pragma unroll
        for (int kk2 = 0; kk2 < 2; kk2++) {
            const uint32_t kb = kk2 * 32;   // 16 bf16 = 32 B

            uint32_t ah[4][4], bh[3][4], bl[3][4];
#pragma unroll
            for (int mt = 0; mt < 4; mt++) ldsm4(ah[mt], aA[mt] + xOff + kb);
#pragma unroll
            for (int p = 0; p < 3; p++)    ldsm4(bh[p], bA[p] + wOff + kb);
#pragma unroll
            for (int p = 0; p < 3; p++)    ldsm4(bl[p], bA[p] + wOff + SM_W * 2 + kb);

            // hi*hi
#pragma unroll
            for (int mt = 0; mt < 4; mt++)
#pragma unroll
                for (int nt = 0; nt < 6; nt++)
                    mma16816(acc[mt][nt], ah[mt],
                             bh[nt >> 1][(nt & 1) * 2], bh[nt >> 1][(nt & 1) * 2 + 1]);
            // hi*lo
#pragma unroll
            for (int mt = 0; mt < 4; mt++)
#pragma unroll
                for (int nt = 0; nt < 6; nt++)
                    mma16816(acc[mt][nt], ah[mt],
                             bl[nt >> 1][(nt & 1) * 2], bl[nt >> 1][(nt & 1) * 2 + 1]);
            // lo*hi
            uint32_t al[4][4];
#pragma unroll
            for (int mt = 0; mt < 4; mt++) ldsm4(al[mt], aA[mt] + xOff + SM_X * 2 + kb);
#pragma unroll
            for (int mt = 0; mt < 4; mt++)
#pragma unroll
                for (int nt = 0; nt < 6; nt++)
                    mma16816(acc[mt][nt], al[mt],
                             bh[nt >> 1][(nt & 1) * 2], bh[nt >> 1][(nt & 1) * 2 + 1]);
        }

        // (e) close the chunk: W(c+1) must have landed; STS X(c+1) visible
        if (c + 1 < NCHUNK) {
            asm volatile("cp.async.wait_group 0;\n" ::: "memory");
            __syncthreads();
        }
    }

    // epilogue: write q|k|v to scratch
#pragma unroll
    for (int mt = 0; mt < 4; mt++) {
#pragma unroll
        for (int nt = 0; nt < 6; nt++) {
            int r  = m0 + warp_m + mt * 16 + g;
            int cn = warp_n + nt * 8 + 2 * tig;
            float2 v0 = make_float2(acc[mt][nt][0], acc[mt][nt][1]);
            float2 v1 = make_float2(acc[mt][nt][2], acc[mt][nt][3]);
            *reinterpret_cast<float2*>(&g_qkv[(size_t)r * NTOT + cn]) = v0;
            *reinterpret_cast<float2*>(&g_qkv[(size_t)(r + 8) * NTOT + cn]) = v1;
        }
    }
}

// ---------------------------------------------------------------- attention
__device__ __forceinline__ float ex2f(float x) {
    float y;
    asm("ex2.approx.ftz.f32 %0, %1;" : "=f"(y) : "f"(x));
    return y;
}

__global__ void __launch_bounds__(256)
attn_kernel(float* __restrict__ out) {
    __shared__ float ks[4][64];
    __shared__ float vs[4][64];
    const int tid = threadIdx.x;
    const int tl = tid >> 6;
    const int i  = tid & 63;
    const size_t tok = (size_t)blockIdx.x * 4 + tl;
    const float* base = g_qkv + tok * NTOT;

    float q = base[i] * 1.4426950408889634f;   // fold log2(e)
    ks[tl][i] = base[64 + i];
    vs[tl][i] = base[128 + i];
    __syncthreads();

    float mx = -1e30f;
#pragma unroll
    for (int j = 0; j < 64; j++) mx = fmaxf(mx, q * ks[tl][j]);

    float s = 0.f, num = 0.f;
#pragma unroll
    for (int j = 0; j < 64; j++) {
        float e = ex2f(fmaf(q, ks[tl][j], -mx));
        s += e;
        num = fmaf(e, vs[tl][j], num);
    }
    out[tok * 64 + i] = num / s;
}

// ----------------------------------------------------------------
extern "C" void kernel_launch(void* const* d_in, const int* in_sizes, int n_in,
                              void* d_out, int out_size) {
    const float* X  = (const float*)d_in[0];
    const float* Wq = (const float*)d_in[1];
    const float* Wk = (const float*)d_in[2];
    const float* Wv = (const float*)d_in[3];
    float* out = (float*)d_out;

    cudaFuncSetAttribute(qkv_gemm, cudaFuncAttributeMaxDynamicSharedMemorySize,
                         SMEM_BYTES);

    prep_w<<<192, 256>>>(Wq, Wk, Wv);
    qkv_gemm<<<M_TOK / BM, 256, SMEM_BYTES>>>(X);
    attn_kernel<<<M_TOK / 4, 256>>>(out);
}

// round 5
// speedup vs baseline: 1.3771x; 1.2658x over previous
#include <cuda_runtime.h>
#include <cuda_fp16.h>
#include <cstdint>

// Problem shapes (fixed by the dataset)
constexpr int M_TOK = 16384;   // b*s = 4*4096
constexpr int KDIM  = 2048;    // h
constexpr int NTOT  = 192;     // q|k|v concatenated

// GEMM tiling
constexpr int BM = 128;
constexpr int BN = 192;
constexpr int BK = 32;
constexpr int PAD_K = 40;      // row = 80 B (16B-aligned, LDSM conflict-free)
constexpr int NCHUNK = KDIM / BK;  // 64

constexpr int SM_X = BM * PAD_K;   // 5120 fp16 (X hi only)
constexpr int SM_W = BN * PAD_K;   // 7680 fp16 (one W half: hi or lo)

// X: 2 buffers (hi only). W: 2 buffers of {hi, lo}.
constexpr int XBUF_STRIDE_B = SM_X * 2;           // 10240 B
constexpr int WBUF_STRIDE_B = 2 * SM_W * 2;       // 30720 B
constexpr int OFF_X_B = 0;
constexpr int OFF_W_B = 2 * XBUF_STRIDE_B;        // 20480
constexpr int SMEM_BYTES = 2 * XBUF_STRIDE_B + 2 * WBUF_STRIDE_B;  // 81920 B

// Scratch
__device__ __half g_Wt_hi[(size_t)NTOT * KDIM];   // [n][k]
__device__ __half g_Wt_lo[(size_t)NTOT * KDIM];
__device__ float g_qkv[(size_t)M_TOK * NTOT];

// ---------------------------------------------------------------- helpers
__device__ __forceinline__ void mma16816(float (&c)[4], const uint32_t (&a)[4],
                                         uint32_t b0, uint32_t b1) {
    asm volatile(
        "mma.sync.aligned.m16n8k16.row.col.f32.f16.f16.f32 "
        "{%0,%1,%2,%3}, {%4,%5,%6,%7}, {%8,%9}, {%0,%1,%2,%3};\n"
        : "+f"(c[0]), "+f"(c[1]), "+f"(c[2]), "+f"(c[3])
        : "r"(a[0]), "r"(a[1]), "r"(a[2]), "r"(a[3]), "r"(b0), "r"(b1));
}
__device__ __forceinline__ void ldsm4(uint32_t (&r)[4], uint32_t addr) {
    asm volatile("ldmatrix.sync.aligned.m8n8.x4.shared.b16 {%0,%1,%2,%3}, [%4];"
                 : "=r"(r[0]), "=r"(r[1]), "=r"(r[2]), "=r"(r[3]) : "r"(addr));
}
__device__ __forceinline__ void cp_async16(uint32_t dst, const void* src) {
    asm volatile("cp.async.cg.shared.global [%0], [%1], 16;\n" :: "r"(dst), "l"(src) : "memory");
}
__device__ __forceinline__ void cp_commit() {
    asm volatile("cp.async.commit_group;\n" ::: "memory");
}
__device__ __forceinline__ uint32_t cvt_f16x2(float a, float b) {  // pack (a lo, b hi)
    uint32_t r;
    asm("cvt.rn.f16x2.f32 %0, %1, %2;" : "=r"(r) : "f"(b), "f"(a));
    return r;
}

// ---------------------------------------------------------------- prep_w
// Tiled transpose W(h,z) -> Wt[n][k] + fp16 hi/lo split. 192 blocks.
__global__ void prep_w(const float* __restrict__ Wq,
                       const float* __restrict__ Wk,
                       const float* __restrict__ Wv) {
    __shared__ float s[32][65];
    const int m  = blockIdx.x / 64;          // matrix
    const int k0 = (blockIdx.x % 64) * 32;   // k tile
    const float* W = (m == 0) ? Wq : ((m == 1) ? Wk : Wv);
    const int t = threadIdx.x;
#pragma unroll
    for (int i = 0; i < 8; i++) {
        int u = t + i * 256;
        int kl = u >> 6, z = u & 63;
        s[kl][z] = W[(size_t)(k0 + kl) * 64 + z];   // coalesced read
    }
    __syncthreads();
#pragma unroll
    for (int i = 0; i < 8; i++) {
        int u = t + i * 256;
        int z = u >> 5, kl = u & 31;
        float w = s[kl][z];
        __half hi = __float2half_rn(w);
        float lo = w - __half2float(hi);
        size_t o = (size_t)(m * 64 + z) * KDIM + k0 + kl;  // coalesced write
        g_Wt_hi[o] = hi;
        g_Wt_lo[o] = __float2half_rn(lo);
    }
}

// ---------------------------------------------------------------- QKV GEMM
// C = X_fp16 * (Wh + Wl)^T : two HMMA passes per k16.
__global__ void __launch_bounds__(256, 1)
qkv_gemm(const float* __restrict__ X) {
    extern __shared__ __half smem[];
    const uint32_t sbase = (uint32_t)__cvta_generic_to_shared(smem);

    const int tid  = threadIdx.x;
    const int lane = tid & 31;
    const int wid  = tid >> 5;
    const int g    = lane >> 2;
    const int tig  = lane & 3;
    const int warp_m = (wid & 1) * 64;
    const int warp_n = (wid >> 1) * 48;
    const int m0 = blockIdx.x * BM;

    // ldmatrix lane-address components
    const int lrow = lane & 7;
    const int lbit3 = (lane >> 3) & 1;
    const int lbit4 = (lane >> 4) & 1;

    // A fragment base addrs (buffer 0)
    uint32_t aA[4];
#pragma unroll
    for (int mt = 0; mt < 4; mt++) {
        int row = warp_m + mt * 16 + lrow + lbit3 * 8;
        aA[mt] = sbase + OFF_X_B + (uint32_t)row * 80u + (uint32_t)lbit4 * 16u;
    }
    // B fragment base addrs (buffer 0); lo at +SM_W*2
    uint32_t bA[3];
#pragma unroll
    for (int p = 0; p < 3; p++) {
        int row = warp_n + p * 16 + lrow + lbit4 * 8;
        bA[p] = sbase + OFF_W_B + (uint32_t)row * 80u + (uint32_t)lbit3 * 16u;
    }

    // X load/store assignment: 2 threads per row, 16 consecutive floats
    const int xr = tid >> 1;
    const int xk = (tid & 1) * 16;
    const uint32_t xsts = sbase + OFF_X_B + (uint32_t)xr * 80u + (uint32_t)xk * 2u;
    const float* xsrc_row = X + (size_t)(m0 + xr) * KDIM + xk;

    const uint32_t wdst0 = sbase + OFF_W_B;

    float acc[4][6][4];
#pragma unroll
    for (int mt = 0; mt < 4; mt++)
#pragma unroll
        for (int nt = 0; nt < 6; nt++)
#pragma unroll
            for (int r = 0; r < 4; r++) acc[mt][nt][r] = 0.f;

    float4 xf[4];

    // convert xf -> fp16 and STS into X buffer `dOff`
    auto convert_sts = [&](uint32_t dOff) {
        uint32_t hw[8];
        hw[0] = cvt_f16x2(xf[0].x, xf[0].y);
        hw[1] = cvt_f16x2(xf[0].z, xf[0].w);
        hw[2] = cvt_f16x2(xf[1].x, xf[1].y);
        hw[3] = cvt_f16x2(xf[1].z, xf[1].w);
        hw[4] = cvt_f16x2(xf[2].x, xf[2].y);
        hw[5] = cvt_f16x2(xf[2].z, xf[2].w);
        hw[6] = cvt_f16x2(xf[3].x, xf[3].y);
        hw[7] = cvt_f16x2(xf[3].z, xf[3].w);
        uint32_t dh = xsts + dOff;
        asm volatile("st.shared.v4.b32 [%0], {%1,%2,%3,%4};" ::
                     "r"(dh), "r"(hw[0]), "r"(hw[1]), "r"(hw[2]), "r"(hw[3]));
        asm volatile("st.shared.v4.b32 [%0], {%1,%2,%3,%4};" ::
                     "r"(dh + 16), "r"(hw[4]), "r"(hw[5]), "r"(hw[6]), "r"(hw[7]));
    };

    auto ldg_x = [&](int c) {
        const float4* p = reinterpret_cast<const float4*>(xsrc_row + (size_t)c * BK);
        xf[0] = p[0]; xf[1] = p[1]; xf[2] = p[2]; xf[3] = p[3];
    };

    auto issue_w = [&](int c) {   // cp.async W(c) into wbuf[c&1]
        const size_t koff = (size_t)c * BK;
        const uint32_t dOff = (uint32_t)(c & 1) * WBUF_STRIDE_B;
#pragma unroll
        for (int r = 0; r < 3; r++) {
            int u = tid + r * 256;
            int n = u >> 2, q = u & 3;
            uint32_t d = wdst0 + dOff + (uint32_t)n * 80u + (uint32_t)q * 16u;
            cp_async16(d, g_Wt_hi + (size_t)n * KDIM + koff + q * 8);
            cp_async16(d + SM_W * 2, g_Wt_lo + (size_t)n * KDIM + koff + q * 8);
        }
        cp_commit();
    };

    // --- prologue ---
    issue_w(0);
    ldg_x(0);
    convert_sts(0);
    ldg_x(1);
    asm volatile("cp.async.wait_group 0;\n" ::: "memory");
    __syncthreads();

#pragma unroll 1
    for (int c = 0; c < NCHUNK; ++c) {
        const uint32_t xOff = (uint32_t)(c & 1) * XBUF_STRIDE_B;
        const uint32_t wOff = (uint32_t)(c & 1) * WBUF_STRIDE_B;

        // (a) store X(c+1) into the idle x buffer
        if (c + 1 < NCHUNK) convert_sts((uint32_t)((c + 1) & 1) * XBUF_STRIDE_B);
        // (b) prefetch X(c+2)
        if (c + 2 < NCHUNK) ldg_x(c + 2);
        // (c) prefetch W(c+1)
        if (c + 1 < NCHUNK) issue_w(c + 1);

        // (d) compute chunk c: two passes (X*Whi, X*Wlo)
#pragma unroll
        for (int kk2 = 0; kk2 < 2; kk2++) {
            const uint32_t kb = kk2 * 32;   // 16 fp16 = 32 B

            uint32_t ah[4][4], bh[3][4], bl[3][4];
#pragma unroll
            for (int mt = 0; mt < 4; mt++) ldsm4(ah[mt], aA[mt] + xOff + kb);
#pragma unroll
            for (int p = 0; p < 3; p++)    ldsm4(bh[p], bA[p] + wOff + kb);
#pragma unroll
            for (int p = 0; p < 3; p++)    ldsm4(bl[p], bA[p] + wOff + SM_W * 2 + kb);

            // pass 1: X * W_hi
#pragma unroll
            for (int mt = 0; mt < 4; mt++)
#pragma unroll
                for (int nt = 0; nt < 6; nt++)
                    mma16816(acc[mt][nt], ah[mt],
                             bh[nt >> 1][(nt & 1) * 2], bh[nt >> 1][(nt & 1) * 2 + 1]);
            // pass 2: X * W_lo
#pragma unroll
            for (int mt = 0; mt < 4; mt++)
#pragma unroll
                for (int nt = 0; nt < 6; nt++)
                    mma16816(acc[mt][nt], ah[mt],
                             bl[nt >> 1][(nt & 1) * 2], bl[nt >> 1][(nt & 1) * 2 + 1]);
        }

        // (e) close chunk
        if (c + 1 < NCHUNK) {
            asm volatile("cp.async.wait_group 0;\n" ::: "memory");
            __syncthreads();
        }
    }

    // epilogue: write q|k|v to scratch
#pragma unroll
    for (int mt = 0; mt < 4; mt++) {
#pragma unroll
        for (int nt = 0; nt < 6; nt++) {
            int r  = m0 + warp_m + mt * 16 + g;
            int cn = warp_n + nt * 8 + 2 * tig;
            float2 v0 = make_float2(acc[mt][nt][0], acc[mt][nt][1]);
            float2 v1 = make_float2(acc[mt][nt][2], acc[mt][nt][3]);
            *reinterpret_cast<float2*>(&g_qkv[(size_t)r * NTOT + cn]) = v0;
            *reinterpret_cast<float2*>(&g_qkv[(size_t)(r + 8) * NTOT + cn]) = v1;
        }
    }
}

// ---------------------------------------------------------------- attention
__device__ __forceinline__ float ex2f(float x) {
    float y;
    asm("ex2.approx.ftz.f32 %0, %1;" : "=f"(y) : "f"(x));
    return y;
}

__global__ void __launch_bounds__(256)
attn_kernel(float* __restrict__ out) {
    __shared__ float ks[4][64];
    __shared__ float vs[4][64];
    const int tid = threadIdx.x;
    const int tl = tid >> 6;
    const int i  = tid & 63;
    const size_t tok = (size_t)blockIdx.x * 4 + tl;
    const float* base = g_qkv + tok * NTOT;

    float q = base[i] * 1.4426950408889634f;   // fold log2(e)
    ks[tl][i] = base[64 + i];
    vs[tl][i] = base[128 + i];
    __syncthreads();

    float mx = -1e30f;
#pragma unroll
    for (int j = 0; j < 64; j++) mx = fmaxf(mx, q * ks[tl][j]);

    float s = 0.f, num = 0.f;
#pragma unroll
    for (int j = 0; j < 64; j++) {
        float e = ex2f(fmaf(q, ks[tl][j], -mx));
        s += e;
        num = fmaf(e, vs[tl][j], num);
    }
    out[tok * 64 + i] = num / s;
}

// ----------------------------------------------------------------
extern "C" void kernel_launch(void* const* d_in, const int* in_sizes, int n_in,
                              void* d_out, int out_size) {
    const float* X  = (const float*)d_in[0];
    const float* Wq = (const float*)d_in[1];
    const float* Wk = (const float*)d_in[2];
    const float* Wv = (const float*)d_in[3];
    float* out = (float*)d_out;

    cudaFuncSetAttribute(qkv_gemm, cudaFuncAttributeMaxDynamicSharedMemorySize,
                         SMEM_BYTES);

    prep_w<<<192, 256>>>(Wq, Wk, Wv);
    qkv_gemm<<<M_TOK / BM, 256, SMEM_BYTES>>>(X);
    attn_kernel<<<M_TOK / 4, 256>>>(out);
}

// round 6
// speedup vs baseline: 1.9454x; 1.4127x over previous
#include <cuda_runtime.h>
#include <cuda_fp16.h>
#include <cstdint>

// Problem shapes (fixed by the dataset)
constexpr int M_TOK = 16384;   // b*s = 4*4096
constexpr int KDIM  = 2048;    // h
constexpr int NTOT  = 192;     // q|k|v concatenated

// GEMM tiling
constexpr int BM = 128;
constexpr int BN = 192;
constexpr int BK = 32;
constexpr int PAD_K = 40;      // row = 80 B (16B-aligned, LDSM conflict-free)
constexpr int NCHUNK = KDIM / BK;  // 64

constexpr int SM_X = BM * PAD_K;   // 5120 fp16
constexpr int SM_W = BN * PAD_K;   // 7680 fp16

// X: 2 buffers. W: 2 buffers (hi only).
constexpr int XBUF_STRIDE_B = SM_X * 2;           // 10240 B
constexpr int WBUF_STRIDE_B = SM_W * 2;           // 15360 B
constexpr int OFF_X_B = 0;
constexpr int OFF_W_B = 2 * XBUF_STRIDE_B;        // 20480
constexpr int SMEM_BYTES = 2 * XBUF_STRIDE_B + 2 * WBUF_STRIDE_B;  // 51200 B

// Scratch
__device__ __half g_Wt[(size_t)NTOT * KDIM];      // [n][k], fp16
__device__ float g_qkv[(size_t)M_TOK * NTOT];

// ---------------------------------------------------------------- helpers
__device__ __forceinline__ void mma16816(float (&c)[4], const uint32_t (&a)[4],
                                         uint32_t b0, uint32_t b1) {
    asm volatile(
        "mma.sync.aligned.m16n8k16.row.col.f32.f16.f16.f32 "
        "{%0,%1,%2,%3}, {%4,%5,%6,%7}, {%8,%9}, {%0,%1,%2,%3};\n"
        : "+f"(c[0]), "+f"(c[1]), "+f"(c[2]), "+f"(c[3])
        : "r"(a[0]), "r"(a[1]), "r"(a[2]), "r"(a[3]), "r"(b0), "r"(b1));
}
__device__ __forceinline__ void ldsm4(uint32_t (&r)[4], uint32_t addr) {
    asm volatile("ldmatrix.sync.aligned.m8n8.x4.shared.b16 {%0,%1,%2,%3}, [%4];"
                 : "=r"(r[0]), "=r"(r[1]), "=r"(r[2]), "=r"(r[3]) : "r"(addr));
}
__device__ __forceinline__ void cp_async16(uint32_t dst, const void* src) {
    asm volatile("cp.async.cg.shared.global [%0], [%1], 16;\n" :: "r"(dst), "l"(src) : "memory");
}
__device__ __forceinline__ void cp_commit() {
    asm volatile("cp.async.commit_group;\n" ::: "memory");
}
__device__ __forceinline__ uint32_t cvt_f16x2(float a, float b) {  // pack (a lo, b hi)
    uint32_t r;
    asm("cvt.rn.f16x2.f32 %0, %1, %2;" : "=r"(r) : "f"(b), "f"(a));
    return r;
}

// ---------------------------------------------------------------- prep_w
// Tiled transpose W(h,z) -> Wt[n][k], fp16. 192 blocks x 256.
__global__ void prep_w(const float* __restrict__ Wq,
                       const float* __restrict__ Wk,
                       const float* __restrict__ Wv) {
    __shared__ float s[32][65];
    const int m  = blockIdx.x / 64;          // matrix
    const int k0 = (blockIdx.x % 64) * 32;   // k tile
    const float* W = (m == 0) ? Wq : ((m == 1) ? Wk : Wv);
    const int t = threadIdx.x;
#pragma unroll
    for (int i = 0; i < 8; i++) {
        int u = t + i * 256;
        int kl = u >> 6, z = u & 63;
        s[kl][z] = W[(size_t)(k0 + kl) * 64 + z];   // coalesced read
    }
    __syncthreads();
#pragma unroll
    for (int i = 0; i < 8; i++) {
        int u = t + i * 256;
        int z = u >> 5, kl = u & 31;
        size_t o = (size_t)(m * 64 + z) * KDIM + k0 + kl;  // coalesced write
        g_Wt[o] = __float2half_rn(s[kl][z]);
    }
}

// ---------------------------------------------------------------- QKV GEMM
// C = X_fp16 * W_fp16^T : one HMMA pass per k16.
__global__ void __launch_bounds__(256, 1)
qkv_gemm(const float* __restrict__ X) {
    extern __shared__ __half smem[];
    const uint32_t sbase = (uint32_t)__cvta_generic_to_shared(smem);

    const int tid  = threadIdx.x;
    const int lane = tid & 31;
    const int wid  = tid >> 5;
    const int g    = lane >> 2;
    const int tig  = lane & 3;
    const int warp_m = (wid & 1) * 64;
    const int warp_n = (wid >> 1) * 48;
    const int m0 = blockIdx.x * BM;

    // ldmatrix lane-address components
    const int lrow = lane & 7;
    const int lbit3 = (lane >> 3) & 1;
    const int lbit4 = (lane >> 4) & 1;

    // A fragment base addrs (buffer 0)
    uint32_t aA[4];
#pragma unroll
    for (int mt = 0; mt < 4; mt++) {
        int row = warp_m + mt * 16 + lrow + lbit3 * 8;
        aA[mt] = sbase + OFF_X_B + (uint32_t)row * 80u + (uint32_t)lbit4 * 16u;
    }
    // B fragment base addrs (buffer 0)
    uint32_t bA[3];
#pragma unroll
    for (int p = 0; p < 3; p++) {
        int row = warp_n + p * 16 + lrow + lbit4 * 8;
        bA[p] = sbase + OFF_W_B + (uint32_t)row * 80u + (uint32_t)lbit3 * 16u;
    }

    // X load/store assignment: 2 threads per row, 16 consecutive floats
    const int xr = tid >> 1;
    const int xk = (tid & 1) * 16;
    const uint32_t xsts = sbase + OFF_X_B + (uint32_t)xr * 80u + (uint32_t)xk * 2u;
    const float* xsrc_row = X + (size_t)(m0 + xr) * KDIM + xk;

    const uint32_t wdst0 = sbase + OFF_W_B;

    float acc[4][6][4];
#pragma unroll
    for (int mt = 0; mt < 4; mt++)
#pragma unroll
        for (int nt = 0; nt < 6; nt++)
#pragma unroll
            for (int r = 0; r < 4; r++) acc[mt][nt][r] = 0.f;

    float4 xf[4];

    auto convert_sts = [&](uint32_t dOff) {
        uint32_t hw[8];
        hw[0] = cvt_f16x2(xf[0].x, xf[0].y);
        hw[1] = cvt_f16x2(xf[0].z, xf[0].w);
        hw[2] = cvt_f16x2(xf[1].x, xf[1].y);
        hw[3] = cvt_f16x2(xf[1].z, xf[1].w);
        hw[4] = cvt_f16x2(xf[2].x, xf[2].y);
        hw[5] = cvt_f16x2(xf[2].z, xf[2].w);
        hw[6] = cvt_f16x2(xf[3].x, xf[3].y);
        hw[7] = cvt_f16x2(xf[3].z, xf[3].w);
        uint32_t dh = xsts + dOff;
        asm volatile("st.shared.v4.b32 [%0], {%1,%2,%3,%4};" ::
                     "r"(dh), "r"(hw[0]), "r"(hw[1]), "r"(hw[2]), "r"(hw[3]));
        asm volatile("st.shared.v4.b32 [%0], {%1,%2,%3,%4};" ::
                     "r"(dh + 16), "r"(hw[4]), "r"(hw[5]), "r"(hw[6]), "r"(hw[7]));
    };

    auto ldg_x = [&](int c) {
        const float4* p = reinterpret_cast<const float4*>(xsrc_row + (size_t)c * BK);
        xf[0] = p[0]; xf[1] = p[1]; xf[2] = p[2]; xf[3] = p[3];
    };

    auto issue_w = [&](int c) {   // cp.async W(c) into wbuf[c&1]
        const size_t koff = (size_t)c * BK;
        const uint32_t dOff = (uint32_t)(c & 1) * WBUF_STRIDE_B;
#pragma unroll
        for (int r = 0; r < 3; r++) {
            int u = tid + r * 256;
            int n = u >> 2, q = u & 3;
            uint32_t d = wdst0 + dOff + (uint32_t)n * 80u + (uint32_t)q * 16u;
            cp_async16(d, g_Wt + (size_t)n * KDIM + koff + q * 8);
        }
        cp_commit();
    };

    // --- prologue ---
    issue_w(0);
    ldg_x(0);
    convert_sts(0);
    ldg_x(1);
    asm volatile("cp.async.wait_group 0;\n" ::: "memory");
    __syncthreads();

#pragma unroll 1
    for (int c = 0; c < NCHUNK; ++c) {
        const uint32_t xOff = (uint32_t)(c & 1) * XBUF_STRIDE_B;
        const uint32_t wOff = (uint32_t)(c & 1) * WBUF_STRIDE_B;

        // (a) store X(c+1) into the idle x buffer
        if (c + 1 < NCHUNK) convert_sts((uint32_t)((c + 1) & 1) * XBUF_STRIDE_B);
        // (b) prefetch X(c+2)
        if (c + 2 < NCHUNK) ldg_x(c + 2);
        // (c) prefetch W(c+1)
        if (c + 1 < NCHUNK) issue_w(c + 1);

        // (d) compute chunk c: single pass
#pragma unroll
        for (int kk2 = 0; kk2 < 2; kk2++) {
            const uint32_t kb = kk2 * 32;   // 16 fp16 = 32 B

            uint32_t ah[4][4], bh[3][4];
#pragma unroll
            for (int mt = 0; mt < 4; mt++) ldsm4(ah[mt], aA[mt] + xOff + kb);
#pragma unroll
            for (int p = 0; p < 3; p++)    ldsm4(bh[p], bA[p] + wOff + kb);

#pragma unroll
            for (int mt = 0; mt < 4; mt++)
#pragma unroll
                for (int nt = 0; nt < 6; nt++)
                    mma16816(acc[mt][nt], ah[mt],
                             bh[nt >> 1][(nt & 1) * 2], bh[nt >> 1][(nt & 1) * 2 + 1]);
        }

        // (e) close chunk
        if (c + 1 < NCHUNK) {
            asm volatile("cp.async.wait_group 0;\n" ::: "memory");
            __syncthreads();
        }
    }

    // epilogue: write q|k|v to scratch
#pragma unroll
    for (int mt = 0; mt < 4; mt++) {
#pragma unroll
        for (int nt = 0; nt < 6; nt++) {
            int r  = m0 + warp_m + mt * 16 + g;
            int cn = warp_n + nt * 8 + 2 * tig;
            float2 v0 = make_float2(acc[mt][nt][0], acc[mt][nt][1]);
            float2 v1 = make_float2(acc[mt][nt][2], acc[mt][nt][3]);
            *reinterpret_cast<float2*>(&g_qkv[(size_t)r * NTOT + cn]) = v0;
            *reinterpret_cast<float2*>(&g_qkv[(size_t)(r + 8) * NTOT + cn]) = v1;
        }
    }
}

// ---------------------------------------------------------------- attention
__device__ __forceinline__ float ex2f(float x) {
    float y;
    asm("ex2.approx.ftz.f32 %0, %1;" : "=f"(y) : "f"(x));
    return y;
}

__global__ void __launch_bounds__(256)
attn_kernel(float* __restrict__ out) {
    __shared__ float ks[4][64];
    __shared__ float vs[4][64];
    const int tid = threadIdx.x;
    const int tl = tid >> 6;
    const int i  = tid & 63;
    const size_t tok = (size_t)blockIdx.x * 4 + tl;
    const float* base = g_qkv + tok * NTOT;

    float q = base[i] * 1.4426950408889634f;   // fold log2(e)
    ks[tl][i] = base[64 + i];
    vs[tl][i] = base[128 + i];
    __syncthreads();

    float mx = -1e30f;
#pragma unroll
    for (int j = 0; j < 64; j++) mx = fmaxf(mx, q * ks[tl][j]);

    float s = 0.f, num = 0.f;
#pragma unroll
    for (int j = 0; j < 64; j++) {
        float e = ex2f(fmaf(q, ks[tl][j], -mx));
        s += e;
        num = fmaf(e, vs[tl][j], num);
    }
    out[tok * 64 + i] = num / s;
}

// ----------------------------------------------------------------
extern "C" void kernel_launch(void* const* d_in, const int* in_sizes, int n_in,
                              void* d_out, int out_size) {
    const float* X  = (const float*)d_in[0];
    const float* Wq = (const float*)d_in[1];
    const float* Wk = (const float*)d_in[2];
    const float* Wv = (const float*)d_in[3];
    float* out = (float*)d_out;

    cudaFuncSetAttribute(qkv_gemm, cudaFuncAttributeMaxDynamicSharedMemorySize,
                         SMEM_BYTES);

    prep_w<<<192, 256>>>(Wq, Wk, Wv);
    qkv_gemm<<<M_TOK / BM, 256, SMEM_BYTES>>>(X);
    attn_kernel<<<M_TOK / 4, 256>>>(out);
}

// round 7
// speedup vs baseline: 2.0520x; 1.0548x over previous
#include <cuda_runtime.h>
#include <cuda_fp16.h>
#include <cstdint>

// Problem shapes (fixed by the dataset)
constexpr int M_TOK = 16384;   // b*s = 4*4096
constexpr int KDIM  = 2048;    // h
constexpr int NTOT  = 192;     // q|k|v concatenated

// GEMM tiling — BM=64 for 2 CTAs/SM
constexpr int BM = 64;
constexpr int BN = 192;
constexpr int BK = 32;
constexpr int PAD_K = 40;      // row = 80 B (16B-aligned, LDSM conflict-free)
constexpr int NCHUNK = KDIM / BK;  // 64

constexpr int SM_X = BM * PAD_K;   // 2560 fp16
constexpr int SM_W = BN * PAD_K;   // 7680 fp16

constexpr int XBUF_STRIDE_B = SM_X * 2;           // 5120 B
constexpr int WBUF_STRIDE_B = SM_W * 2;           // 15360 B
constexpr int OFF_X_B = 0;
constexpr int OFF_W_B = 2 * XBUF_STRIDE_B;        // 10240
constexpr int SMEM_BYTES = 2 * XBUF_STRIDE_B + 2 * WBUF_STRIDE_B;  // 40960 B

// Scratch
__device__ __half g_Wt[(size_t)NTOT * KDIM];      // [n][k], fp16
__device__ float g_qkv[(size_t)M_TOK * NTOT];

// ---------------------------------------------------------------- helpers
__device__ __forceinline__ void mma16816(float (&c)[4], const uint32_t (&a)[4],
                                         uint32_t b0, uint32_t b1) {
    asm volatile(
        "mma.sync.aligned.m16n8k16.row.col.f32.f16.f16.f32 "
        "{%0,%1,%2,%3}, {%4,%5,%6,%7}, {%8,%9}, {%0,%1,%2,%3};\n"
        : "+f"(c[0]), "+f"(c[1]), "+f"(c[2]), "+f"(c[3])
        : "r"(a[0]), "r"(a[1]), "r"(a[2]), "r"(a[3]), "r"(b0), "r"(b1));
}
__device__ __forceinline__ void ldsm4(uint32_t (&r)[4], uint32_t addr) {
    asm volatile("ldmatrix.sync.aligned.m8n8.x4.shared.b16 {%0,%1,%2,%3}, [%4];"
                 : "=r"(r[0]), "=r"(r[1]), "=r"(r[2]), "=r"(r[3]) : "r"(addr));
}
__device__ __forceinline__ void cp_async16(uint32_t dst, const void* src) {
    asm volatile("cp.async.cg.shared.global [%0], [%1], 16;\n" :: "r"(dst), "l"(src) : "memory");
}
__device__ __forceinline__ void cp_commit() {
    asm volatile("cp.async.commit_group;\n" ::: "memory");
}
__device__ __forceinline__ uint32_t cvt_f16x2(float a, float b) {  // pack (a lo, b hi)
    uint32_t r;
    asm("cvt.rn.f16x2.f32 %0, %1, %2;" : "=r"(r) : "f"(b), "f"(a));
    return r;
}

// ---------------------------------------------------------------- prep_w
// Tiled transpose W(h,z) -> Wt[n][k], fp16. 192 blocks x 256.
__global__ void prep_w(const float* __restrict__ Wq,
                       const float* __restrict__ Wk,
                       const float* __restrict__ Wv) {
    __shared__ float s[32][65];
    const int m  = blockIdx.x / 64;          // matrix
    const int k0 = (blockIdx.x % 64) * 32;   // k tile
    const float* W = (m == 0) ? Wq : ((m == 1) ? Wk : Wv);
    const int t = threadIdx.x;
#pragma unroll
    for (int i = 0; i < 8; i++) {
        int u = t + i * 256;
        int kl = u >> 6, z = u & 63;
        s[kl][z] = W[(size_t)(k0 + kl) * 64 + z];   // coalesced read
    }
    __syncthreads();
#pragma unroll
    for (int i = 0; i < 8; i++) {
        int u = t + i * 256;
        int z = u >> 5, kl = u & 31;
        size_t o = (size_t)(m * 64 + z) * KDIM + k0 + kl;  // coalesced write
        g_Wt[o] = __float2half_rn(s[kl][z]);
    }
}

// ---------------------------------------------------------------- QKV GEMM
// C = X_fp16 * W_fp16^T, BM=64 tiles, 2 CTAs/SM.
__global__ void __launch_bounds__(256, 2)
qkv_gemm(const float* __restrict__ X) {
    extern __shared__ __half smem[];
    const uint32_t sbase = (uint32_t)__cvta_generic_to_shared(smem);

    const int tid  = threadIdx.x;
    const int lane = tid & 31;
    const int wid  = tid >> 5;
    const int g    = lane >> 2;
    const int tig  = lane & 3;
    const int warp_m = (wid & 1) * 32;     // 2 warp rows of 32
    const int warp_n = (wid >> 1) * 48;    // 4 warp cols of 48
    const int m0 = blockIdx.x * BM;

    // ldmatrix lane-address components
    const int lrow = lane & 7;
    const int lbit3 = (lane >> 3) & 1;
    const int lbit4 = (lane >> 4) & 1;

    // A fragment base addrs (buffer 0)
    uint32_t aA[2];
#pragma unroll
    for (int mt = 0; mt < 2; mt++) {
        int row = warp_m + mt * 16 + lrow + lbit3 * 8;
        aA[mt] = sbase + OFF_X_B + (uint32_t)row * 80u + (uint32_t)lbit4 * 16u;
    }
    // B fragment base addrs (buffer 0)
    uint32_t bA[3];
#pragma unroll
    for (int p = 0; p < 3; p++) {
        int row = warp_n + p * 16 + lrow + lbit4 * 8;
        bA[p] = sbase + OFF_W_B + (uint32_t)row * 80u + (uint32_t)lbit3 * 16u;
    }

    // X load/store: 4 threads per row, 8 consecutive floats each
    const int xr = tid >> 2;              // 0..63
    const int xk = (tid & 3) * 8;         // 0,8,16,24
    const uint32_t xsts = sbase + OFF_X_B + (uint32_t)xr * 80u + (uint32_t)xk * 2u;
    const float* xsrc_row = X + (size_t)(m0 + xr) * KDIM + xk;

    const uint32_t wdst0 = sbase + OFF_W_B;

    float acc[2][6][4];
#pragma unroll
    for (int mt = 0; mt < 2; mt++)
#pragma unroll
        for (int nt = 0; nt < 6; nt++)
#pragma unroll
            for (int r = 0; r < 4; r++) acc[mt][nt][r] = 0.f;

    float4 xf[2];

    auto convert_sts = [&](uint32_t dOff) {
        uint32_t hw[4];
        hw[0] = cvt_f16x2(xf[0].x, xf[0].y);
        hw[1] = cvt_f16x2(xf[0].z, xf[0].w);
        hw[2] = cvt_f16x2(xf[1].x, xf[1].y);
        hw[3] = cvt_f16x2(xf[1].z, xf[1].w);
        asm volatile("st.shared.v4.b32 [%0], {%1,%2,%3,%4};" ::
                     "r"(xsts + dOff), "r"(hw[0]), "r"(hw[1]), "r"(hw[2]), "r"(hw[3]));
    };

    auto ldg_x = [&](int c) {
        const float4* p = reinterpret_cast<const float4*>(xsrc_row + (size_t)c * BK);
        xf[0] = p[0]; xf[1] = p[1];
    };

    auto issue_w = [&](int c) {   // cp.async W(c) into wbuf[c&1]
        const size_t koff = (size_t)c * BK;
        const uint32_t dOff = (uint32_t)(c & 1) * WBUF_STRIDE_B;
#pragma unroll
        for (int r = 0; r < 3; r++) {
            int u = tid + r * 256;
            int n = u >> 2, q = u & 3;
            uint32_t d = wdst0 + dOff + (uint32_t)n * 80u + (uint32_t)q * 16u;
            cp_async16(d, g_Wt + (size_t)n * KDIM + koff + q * 8);
        }
        cp_commit();
    };

    // --- prologue ---
    issue_w(0);
    ldg_x(0);
    convert_sts(0);
    ldg_x(1);
    asm volatile("cp.async.wait_group 0;\n" ::: "memory");
    __syncthreads();

#pragma unroll 1
    for (int c = 0; c < NCHUNK; ++c) {
        const uint32_t xOff = (uint32_t)(c & 1) * XBUF_STRIDE_B;
        const uint32_t wOff = (uint32_t)(c & 1) * WBUF_STRIDE_B;

        // (a) store X(c+1) into the idle x buffer
        if (c + 1 < NCHUNK) convert_sts((uint32_t)((c + 1) & 1) * XBUF_STRIDE_B);
        // (b) prefetch X(c+2)
        if (c + 2 < NCHUNK) ldg_x(c + 2);
        // (c) prefetch W(c+1)
        if (c + 1 < NCHUNK) issue_w(c + 1);

        // (d) compute chunk c
#pragma unroll
        for (int kk2 = 0; kk2 < 2; kk2++) {
            const uint32_t kb = kk2 * 32;   // 16 fp16 = 32 B

            uint32_t ah[2][4], bh[3][4];
#pragma unroll
            for (int mt = 0; mt < 2; mt++) ldsm4(ah[mt], aA[mt] + xOff + kb);
#pragma unroll
            for (int p = 0; p < 3; p++)    ldsm4(bh[p], bA[p] + wOff + kb);

#pragma unroll
            for (int mt = 0; mt < 2; mt++)
#pragma unroll
                for (int nt = 0; nt < 6; nt++)
                    mma16816(acc[mt][nt], ah[mt],
                             bh[nt >> 1][(nt & 1) * 2], bh[nt >> 1][(nt & 1) * 2 + 1]);
        }

        // (e) close chunk
        if (c + 1 < NCHUNK) {
            asm volatile("cp.async.wait_group 0;\n" ::: "memory");
            __syncthreads();
        }
    }

    // epilogue: write q|k|v to scratch
#pragma unroll
    for (int mt = 0; mt < 2; mt++) {
#pragma unroll
        for (int nt = 0; nt < 6; nt++) {
            int r  = m0 + warp_m + mt * 16 + g;
            int cn = warp_n + nt * 8 + 2 * tig;
            float2 v0 = make_float2(acc[mt][nt][0], acc[mt][nt][1]);
            float2 v1 = make_float2(acc[mt][nt][2], acc[mt][nt][3]);
            *reinterpret_cast<float2*>(&g_qkv[(size_t)r * NTOT + cn]) = v0;
            *reinterpret_cast<float2*>(&g_qkv[(size_t)(r + 8) * NTOT + cn]) = v1;
        }
    }
}

// ---------------------------------------------------------------- attention
__device__ __forceinline__ float ex2f(float x) {
    float y;
    asm("ex2.approx.ftz.f32 %0, %1;" : "=f"(y) : "f"(x));
    return y;
}

__global__ void __launch_bounds__(256)
attn_kernel(float* __restrict__ out) {
    __shared__ float ks[4][64];
    __shared__ float vs[4][64];
    const int tid = threadIdx.x;
    const int tl = tid >> 6;
    const int i  = tid & 63;
    const size_t tok = (size_t)blockIdx.x * 4 + tl;
    const float* base = g_qkv + tok * NTOT;

    float q = base[i] * 1.4426950408889634f;   // fold log2(e)
    ks[tl][i] = base[64 + i];
    vs[tl][i] = base[128 + i];
    __syncthreads();

    float mx = -1e30f;
#pragma unroll
    for (int j = 0; j < 64; j++) mx = fmaxf(mx, q * ks[tl][j]);

    float s = 0.f, num = 0.f;
#pragma unroll
    for (int j = 0; j < 64; j++) {
        float e = ex2f(fmaf(q, ks[tl][j], -mx));
        s += e;
        num = fmaf(e, vs[tl][j], num);
    }
    out[tok * 64 + i] = num / s;
}

// ----------------------------------------------------------------
extern "C" void kernel_launch(void* const* d_in, const int* in_sizes, int n_in,
                              void* d_out, int out_size) {
    const float* X  = (const float*)d_in[0];
    const float* Wq = (const float*)d_in[1];
    const float* Wk = (const float*)d_in[2];
    const float* Wv = (const float*)d_in[3];
    float* out = (float*)d_out;

    prep_w<<<192, 256>>>(Wq, Wk, Wv);
    qkv_gemm<<<M_TOK / BM, 256, SMEM_BYTES>>>(X);
    attn_kernel<<<M_TOK / 4, 256>>>(out);
}